// round 11
// baseline (speedup 1.0000x reference)
#include <cuda_runtime.h>
#include <cuda_bf16.h>
#include <cstdint>

#define N_TOK  65529
#define NPAD   65536
#define CDIM   1024
#define QKV_N  3072
#define HEADS  16
#define HD     64
#define HDP    68
#define KTOK   32
#define AW     2

// gemm config: 128x128 CTA tile, 8 warps (2x4), 64x32 per warp, BK=16,
// 3-stage cp.async pipeline, dynamic smem.
#define GT   256
#define ASTR 20
#define BSTR 136
#define STAGE_WORDS (128 * ASTR + 16 * BSTR)    // 4736 words = 18944 B
#define NSTAGE 3
#define SMEM_REQ (NSTAGE * STAGE_WORDS * 4)     // 56832 B

// Scratch: qkv (attention output overwrites Q region), plus pre-rounded
// tf32 copies of data / w_qkv / w_proj.
#define AUX_DATA  0
#define AUX_WQKV  ((size_t)NPAD * CDIM)
#define AUX_WPROJ (AUX_WQKV + (size_t)CDIM * QKV_N)
#define AUX_TOTAL (AUX_WPROJ + (size_t)CDIM * CDIM)

__device__ float g_qkv[(size_t)NPAD * QKV_N];   // 805 MB
__device__ float g_aux[AUX_TOTAL];              // 285 MB
__device__ int   g_idx64;

// ---------------------------------------------------------------------------
__global__ void detect_idx_kernel(const int* __restrict__ b) {
    __shared__ int s;
    if (threadIdx.x == 0) s = 0;
    __syncthreads();
    int local = 0;
    for (int i = threadIdx.x; i < (N_TOK / 2) - 1; i += blockDim.x) {
        int lo = b[2 * i], hi = b[2 * i + 1];
        if (lo > 0 && hi == 0) local = 1;
    }
    if (local) atomicOr(&s, 1);
    __syncthreads();
    if (threadIdx.x == 0) g_idx64 = s;
}

// ---------------------------------------------------------------------------
__device__ __forceinline__ uint32_t f2tf(float f) {
    uint32_t r;
    asm("cvt.rna.tf32.f32 %0, %1;" : "=r"(r) : "f"(f));
    return r;
}
__device__ __forceinline__ float f2tf_f(float f) {
    return __uint_as_float(f2tf(f));
}

// RNA-round src[0..n4r) into dst; zero dst[n4r..n4t). float4 granularity.
__global__ void round_kernel(const float4* __restrict__ src,
                             float4* __restrict__ dst, int n4r, int n4t)
{
    const int i = blockIdx.x * blockDim.x + threadIdx.x;
    if (i >= n4t) return;
    float4 o = make_float4(0.f, 0.f, 0.f, 0.f);
    if (i < n4r) {
        const float4 v = src[i];
        o.x = f2tf_f(v.x); o.y = f2tf_f(v.y);
        o.z = f2tf_f(v.z); o.w = f2tf_f(v.w);
    }
    dst[i] = o;
}

// ---------------------------------------------------------------------------
__device__ __forceinline__ void mma_tf32(float* c, const uint32_t* a, const uint32_t* b) {
    asm volatile(
        "mma.sync.aligned.m16n8k8.row.col.f32.tf32.tf32.f32 "
        "{%0,%1,%2,%3}, {%4,%5,%6,%7}, {%8,%9}, {%0,%1,%2,%3};"
        : "+f"(c[0]), "+f"(c[1]), "+f"(c[2]), "+f"(c[3])
        : "r"(a[0]), "r"(a[1]), "r"(a[2]), "r"(a[3]),
          "r"(b[0]), "r"(b[1]));
}
__device__ __forceinline__ void cp16(uint32_t saddr, const void* g) {
    asm volatile("cp.async.cg.shared.global [%0], [%1], 16;"
                 :: "r"(saddr), "l"(g) : "memory");
}
__device__ __forceinline__ void cp_commit() {
    asm volatile("cp.async.commit_group;" ::: "memory");
}
template <int N>
__device__ __forceinline__ void cp_wait() {
    asm volatile("cp.async.wait_group %0;" :: "n"(N) : "memory");
}

// ---------------------------------------------------------------------------
// TF32 tensor-core GEMM: 128x128 CTA tile, BK=16, 256 threads, 8 warps,
// 64x32 per warp. Inputs PRE-ROUNDED to tf32 (raw bits fed to mma).
// 3-stage cp.async pipeline, dynamic smem.
// C[row,col] = sum_k A[row*lda+k]*B[k*Nc+col] + bias[col]
//   rows >= Mreal   : output forced to exact 0 (A rows are pre-zeroed)
//   rows >= MoutRows: not written
// ---------------------------------------------------------------------------
__global__ __launch_bounds__(GT, 2) void tf32_gemm(
    const float* __restrict__ A, const float* __restrict__ B,
    const float* __restrict__ bias, float* __restrict__ C,
    int Nc, int Kd, int lda, int ldc, int Mreal, int MoutRows)
{
    extern __shared__ uint32_t sm[];

    const int tid  = threadIdx.x;
    const int warp = tid >> 5;
    const int lane = tid & 31;
    const int wRow = warp >> 2;        // 0..1 (64 rows)
    const int wCol = warp & 3;         // 0..3 (32 cols)
    const int g    = lane >> 2;        // 0..7
    const int t4   = lane & 3;         // 0..3
    const int rowBase = blockIdx.y * 128;
    const int colBase = blockIdx.x * 128;

    float acc[4][4][4];
    #pragma unroll
    for (int mt = 0; mt < 4; mt++)
        #pragma unroll
        for (int nt = 0; nt < 4; nt++)
            #pragma unroll
            for (int r = 0; r < 4; r++) acc[mt][nt][r] = 0.0f;

    const uint32_t smBase = (uint32_t)__cvta_generic_to_shared(sm);
    const int NT = Kd >> 4;

    auto fill_async = [&](int buf, int kt) {
        const int k0 = kt * 16;
        const uint32_t aAddr = smBase + (uint32_t)buf * (STAGE_WORDS * 4);
        const uint32_t bAddr = aAddr + 128 * ASTR * 4;
        #pragma unroll
        for (int i = 0; i < 2; i++) {
            const int vec = tid + i * GT;      // 0..511
            const int ar  = vec >> 2;          // 0..127
            const int ac4 = vec & 3;
            cp16(aAddr + (uint32_t)(ar * ASTR + ac4 * 4) * 4,
                 &A[(size_t)(rowBase + ar) * lda + k0 + ac4 * 4]);
            const int br  = vec >> 5;          // 0..15
            const int bc4 = vec & 31;
            cp16(bAddr + (uint32_t)(br * BSTR + bc4 * 4) * 4,
                 &B[(size_t)(k0 + br) * Nc + colBase + bc4 * 4]);
        }
        cp_commit();
    };

    fill_async(0, 0);
    fill_async(1, 1);

    int buf = 0;
    for (int kt = 0; kt < NT; kt++) {
        if (kt + 1 < NT) cp_wait<1>(); else cp_wait<0>();
        __syncthreads();
        if (kt + 2 < NT) {
            int nb = buf + 2; if (nb >= NSTAGE) nb -= NSTAGE;
            fill_async(nb, kt + 2);
        }

        const uint32_t* Ab = sm + buf * STAGE_WORDS;
        const uint32_t* Bb = Ab + 128 * ASTR;
        #pragma unroll
        for (int kk = 0; kk < 2; kk++) {
            uint32_t af[4][4];
            uint32_t bf[4][2];
            #pragma unroll
            for (int mt = 0; mt < 4; mt++) {
                const int r = wRow * 64 + mt * 16 + g;
                const int c = kk * 8 + t4;
                af[mt][0] = Ab[r * ASTR + c];
                af[mt][1] = Ab[(r + 8) * ASTR + c];
                af[mt][2] = Ab[r * ASTR + c + 4];
                af[mt][3] = Ab[(r + 8) * ASTR + c + 4];
            }
            #pragma unroll
            for (int nt = 0; nt < 4; nt++) {
                const int n = wCol * 32 + nt * 8 + g;
                const int k = kk * 8 + t4;
                bf[nt][0] = Bb[k * BSTR + n];
                bf[nt][1] = Bb[(k + 4) * BSTR + n];
            }
            #pragma unroll
            for (int mt = 0; mt < 4; mt++)
                #pragma unroll
                for (int nt = 0; nt < 4; nt++)
                    mma_tf32(acc[mt][nt], af[mt], bf[nt]);
        }
        // all warps must finish reading buf before it can be refilled (t+3);
        // the next iteration's post-wait __syncthreads provides that barrier.
        buf++; if (buf >= NSTAGE) buf = 0;
    }

    // epilogue
    #pragma unroll
    for (int mt = 0; mt < 4; mt++) {
        #pragma unroll
        for (int half = 0; half < 2; half++) {
            const int gr = rowBase + wRow * 64 + mt * 16 + g + half * 8;
            if (gr >= MoutRows) continue;
            const bool pad = (gr >= Mreal);
            #pragma unroll
            for (int nt = 0; nt < 4; nt++) {
                const int gc = colBase + wCol * 32 + nt * 8 + 2 * t4;
                float2 o;
                o.x = pad ? 0.f : acc[mt][nt][half * 2 + 0] + bias[gc + 0];
                o.y = pad ? 0.f : acc[mt][nt][half * 2 + 1] + bias[gc + 1];
                *(float2*)&C[(size_t)gr * ldc + gc] = o;
            }
        }
    }
}

// ---------------------------------------------------------------------------
// Attention: unchanged; in-place output RNA-rounded into the Q region.
// ---------------------------------------------------------------------------
__global__ __launch_bounds__(32 * AW) void attn_kernel(
    const int* __restrict__ bidx, const int* __restrict__ didx)
{
    const int warp = threadIdx.x >> 5;
    const int lane = threadIdx.x & 31;
    const int flat = blockIdx.x * AW + warp;
    const int p = flat >> 4;
    const int h = flat & 15;
    const int group = p >> 2;
    const int dsub  = p & 3;
    const int stride = g_idx64 ? 2 : 1;

    __shared__ float ks[AW][KTOK][HDP];
    __shared__ float vs[AW][KTOK][HDP];
    __shared__ int   sb_[AW][KTOK];
    __shared__ int   sd_[AW][KTOK];

    const int myrow = group * 128 + lane * 4 + dsub;

    if (myrow < N_TOK) {
        sb_[warp][lane] = bidx[(size_t)myrow * stride];
        sd_[warp][lane] = didx[(size_t)myrow * stride];
    } else {
        sb_[warp][lane] = 0;
        sd_[warp][lane] = 0x40000000;
    }

    float* base = &g_qkv[(size_t)myrow * QKV_N];
    {
        const float4* kp = (const float4*)(base + CDIM + h * HD);
        const float4* vp = (const float4*)(base + 2 * CDIM + h * HD);
        #pragma unroll
        for (int i = 0; i < 16; i++) {
            ((float4*)ks[warp][lane])[i] = kp[i];
            ((float4*)vs[warp][lane])[i] = vp[i];
        }
    }
    float4 q[16];
    {
        const float4* qp = (const float4*)(base + h * HD);
        #pragma unroll
        for (int i = 0; i < 16; i++) q[i] = qp[i];
    }
    __syncwarp();

    const int myb = sb_[warp][lane];
    const int myd = sd_[warp][lane];

    float sc[KTOK];
    float mx = -3.4e38f;
    #pragma unroll
    for (int j = 0; j < KTOK; j++) {
        float4 a4 = make_float4(0.f, 0.f, 0.f, 0.f);
        const float4* kj = (const float4*)ks[warp][j];
        #pragma unroll
        for (int i = 0; i < 16; i++) {
            const float4 kv = kj[i];
            a4.x = fmaf(q[i].x, kv.x, a4.x);
            a4.y = fmaf(q[i].y, kv.y, a4.y);
            a4.z = fmaf(q[i].z, kv.z, a4.z);
            a4.w = fmaf(q[i].w, kv.w, a4.w);
        }
        float s = ((a4.x + a4.y) + (a4.z + a4.w)) * 0.125f;
        if (myb != sb_[warp][j]) s -= 1000.0f;
        if (myd <  sd_[warp][j]) s -= 1000.0f;
        sc[j] = s;
        mx = fmaxf(mx, s);
    }

    float sum = 0.0f;
    #pragma unroll
    for (int j = 0; j < KTOK; j++) {
        sc[j] = __expf(sc[j] - mx);
        sum += sc[j];
    }
    const float inv = 1.0f / sum;

    float4 o[16];
    #pragma unroll
    for (int i = 0; i < 16; i++) o[i] = make_float4(0.f, 0.f, 0.f, 0.f);
    #pragma unroll
    for (int j = 0; j < KTOK; j++) {
        const float a = sc[j] * inv;
        const float4* vj = (const float4*)vs[warp][j];
        #pragma unroll
        for (int i = 0; i < 16; i++) {
            const float4 vv = vj[i];
            o[i].x = fmaf(a, vv.x, o[i].x);
            o[i].y = fmaf(a, vv.y, o[i].y);
            o[i].z = fmaf(a, vv.z, o[i].z);
            o[i].w = fmaf(a, vv.w, o[i].w);
        }
    }

    float4* op = (float4*)(base + h * HD);
    #pragma unroll
    for (int i = 0; i < 16; i++) {
        op[i] = make_float4(f2tf_f(o[i].x), f2tf_f(o[i].y),
                            f2tf_f(o[i].z), f2tf_f(o[i].w));
    }
}

// ---------------------------------------------------------------------------
extern "C" void kernel_launch(void* const* d_in, const int* in_sizes, int n_in,
                              void* d_out, int out_size)
{
    const float* data   = (const float*)d_in[0];
    const float* w_qkv  = (const float*)d_in[1];
    const float* b_qkv  = (const float*)d_in[2];
    const float* w_proj = (const float*)d_in[3];
    const float* b_proj = (const float*)d_in[4];
    const int*   bidx   = (const int*)d_in[5];
    const int*   didx   = (const int*)d_in[6];
    (void)in_sizes; (void)n_in; (void)out_size;

    float* qkv_ptr = nullptr;
    float* aux_ptr = nullptr;
    cudaGetSymbolAddress((void**)&qkv_ptr, g_qkv);
    cudaGetSymbolAddress((void**)&aux_ptr, g_aux);
    float* dataR  = aux_ptr + AUX_DATA;
    float* wqkvR  = aux_ptr + AUX_WQKV;
    float* wprojR = aux_ptr + AUX_WPROJ;

    cudaFuncSetAttribute(tf32_gemm, cudaFuncAttributeMaxDynamicSharedMemorySize,
                         SMEM_REQ);

    detect_idx_kernel<<<1, 256>>>(bidx);

    // Pre-round inputs to tf32 (RNA); zero pad rows of data.
    {
        const int n4r = (N_TOK * CDIM) / 4, n4t = (NPAD * CDIM) / 4;
        round_kernel<<<(n4t + 255) / 256, 256>>>((const float4*)data,
                                                 (float4*)dataR, n4r, n4t);
        const int w1 = (CDIM * QKV_N) / 4;
        round_kernel<<<(w1 + 255) / 256, 256>>>((const float4*)w_qkv,
                                                (float4*)wqkvR, w1, w1);
        const int w2 = (CDIM * CDIM) / 4;
        round_kernel<<<(w2 + 255) / 256, 256>>>((const float4*)w_proj,
                                                (float4*)wprojR, w2, w2);
    }

    // qkv = data @ w_qkv + b_qkv, pad rows -> exact 0
    dim3 g1(QKV_N / 128, NPAD / 128);
    tf32_gemm<<<g1, GT, SMEM_REQ>>>(dataR, wqkvR, b_qkv, qkv_ptr,
                                    QKV_N, CDIM, CDIM, QKV_N, N_TOK, NPAD);

    // blocked attention; rounded output in-place into Q region
    attn_kernel<<<(2048 * HEADS) / AW, 32 * AW>>>(bidx, didx);

    // out = attn_out @ w_proj + b_proj (A = Q region of g_qkv, lda=3072)
    dim3 g2(CDIM / 128, NPAD / 128);
    tf32_gemm<<<g2, GT, SMEM_REQ>>>(qkv_ptr, wprojR, b_proj, (float*)d_out,
                                    CDIM, CDIM, QKV_N, CDIM, NPAD, N_TOK);
}

// round 13
// speedup vs baseline: 1.0449x; 1.0449x over previous
#include <cuda_runtime.h>
#include <cuda_bf16.h>
#include <cstdint>

#define N_TOK  65529
#define NPAD   65536
#define CDIM   1024
#define QKV_N  3072
#define HEADS  16
#define HD     64
#define HDP    68
#define KTOK   32
#define AW     2

// gemm config: 128x128 CTA tile, 4 warps, 64x64 per warp, BK=16,
// 2-stage cp.async double buffer, ldmatrix fragment loads.
#define GT    128
#define ASTR  20     // A smem row stride (words), conflict-free for ldmatrix
#define BSTR2 20     // B smem row stride (words), n-major [128 n][16 k]

// Scratch: qkv (attention output overwrites Q region), plus pre-rounded
// tf32 data and pre-rounded TRANSPOSED weights (n-major, for ldmatrix B).
#define AUX_DATA  0
#define AUX_WQKV  ((size_t)NPAD * CDIM)
#define AUX_WPROJ (AUX_WQKV + (size_t)CDIM * QKV_N)
#define AUX_TOTAL (AUX_WPROJ + (size_t)CDIM * CDIM)

__device__ float g_qkv[(size_t)NPAD * QKV_N];   // 805 MB
__device__ float g_aux[AUX_TOTAL];              // 285 MB
__device__ int   g_idx64;

// ---------------------------------------------------------------------------
__global__ void detect_idx_kernel(const int* __restrict__ b) {
    __shared__ int s;
    if (threadIdx.x == 0) s = 0;
    __syncthreads();
    int local = 0;
    for (int i = threadIdx.x; i < (N_TOK / 2) - 1; i += blockDim.x) {
        int lo = b[2 * i], hi = b[2 * i + 1];
        if (lo > 0 && hi == 0) local = 1;
    }
    if (local) atomicOr(&s, 1);
    __syncthreads();
    if (threadIdx.x == 0) g_idx64 = s;
}

// ---------------------------------------------------------------------------
__device__ __forceinline__ uint32_t f2tf(float f) {
    uint32_t r;
    asm("cvt.rna.tf32.f32 %0, %1;" : "=r"(r) : "f"(f));
    return r;
}
__device__ __forceinline__ float f2tf_f(float f) {
    return __uint_as_float(f2tf(f));
}

// RNA-round src[0..n4r) into dst; zero dst[n4r..n4t). float4 granularity.
__global__ void round_kernel(const float4* __restrict__ src,
                             float4* __restrict__ dst, int n4r, int n4t)
{
    const int i = blockIdx.x * blockDim.x + threadIdx.x;
    if (i >= n4t) return;
    float4 o = make_float4(0.f, 0.f, 0.f, 0.f);
    if (i < n4r) {
        const float4 v = src[i];
        o.x = f2tf_f(v.x); o.y = f2tf_f(v.y);
        o.z = f2tf_f(v.z); o.w = f2tf_f(v.w);
    }
    dst[i] = o;
}

// RNA-round + transpose: src[R][C] -> dst[C][R]. R,C multiples of 32.
__global__ void round_transpose(const float* __restrict__ src,
                                float* __restrict__ dst, int R, int C)
{
    __shared__ float t[32][33];
    const int c0 = blockIdx.x * 32, r0 = blockIdx.y * 32;
    #pragma unroll
    for (int i = threadIdx.y; i < 32; i += 8)
        t[i][threadIdx.x] = src[(size_t)(r0 + i) * C + c0 + threadIdx.x];
    __syncthreads();
    #pragma unroll
    for (int i = threadIdx.y; i < 32; i += 8)
        dst[(size_t)(c0 + i) * R + r0 + threadIdx.x] = f2tf_f(t[threadIdx.x][i]);
}

// ---------------------------------------------------------------------------
__device__ __forceinline__ void mma_tf32(float* c, const uint32_t* a, const uint32_t* b) {
    asm volatile(
        "mma.sync.aligned.m16n8k8.row.col.f32.tf32.tf32.f32 "
        "{%0,%1,%2,%3}, {%4,%5,%6,%7}, {%8,%9}, {%0,%1,%2,%3};"
        : "+f"(c[0]), "+f"(c[1]), "+f"(c[2]), "+f"(c[3])
        : "r"(a[0]), "r"(a[1]), "r"(a[2]), "r"(a[3]),
          "r"(b[0]), "r"(b[1]));
}
__device__ __forceinline__ void ldsm4(uint32_t* r, uint32_t addr) {
    asm volatile("ldmatrix.sync.aligned.m8n8.x4.shared.b16 {%0,%1,%2,%3}, [%4];"
                 : "=r"(r[0]), "=r"(r[1]), "=r"(r[2]), "=r"(r[3]) : "r"(addr));
}
__device__ __forceinline__ void ldsm2(uint32_t* r, uint32_t addr) {
    asm volatile("ldmatrix.sync.aligned.m8n8.x2.shared.b16 {%0,%1}, [%2];"
                 : "=r"(r[0]), "=r"(r[1]) : "r"(addr));
}
__device__ __forceinline__ void cp16(uint32_t saddr, const void* g) {
    asm volatile("cp.async.cg.shared.global [%0], [%1], 16;"
                 :: "r"(saddr), "l"(g) : "memory");
}
__device__ __forceinline__ void cp_commit() {
    asm volatile("cp.async.commit_group;" ::: "memory");
}
__device__ __forceinline__ void cp_wait0() {
    asm volatile("cp.async.wait_group 0;" ::: "memory");
}

// ---------------------------------------------------------------------------
// TF32 tensor-core GEMM: 128x128 CTA tile, BK=16, 128 threads, 4 warps,
// 64x64 per warp. Inputs PRE-ROUNDED to tf32 (raw bits fed to mma).
// A: [rows][Kd] row-major (stride lda). Bt: [Nc][Kd] (TRANSPOSED weight).
// Fragment loads via ldmatrix (A: x4, B: x2 on n-major smem).
// C[row,col] = sum_k A[row*lda+k]*Bt[col*Kd+k] + bias[col]
//   rows >= Mreal   : output forced to exact 0 (A rows are pre-zeroed)
//   rows >= MoutRows: not written
// ---------------------------------------------------------------------------
__global__ __launch_bounds__(GT, 2) void tf32_gemm(
    const float* __restrict__ A, const float* __restrict__ Bt,
    const float* __restrict__ bias, float* __restrict__ C,
    int Nc, int Kd, int lda, int ldc, int Mreal, int MoutRows)
{
    __shared__ uint32_t As[2][128 * ASTR];    // 2 x 10240 B
    __shared__ uint32_t Bs[2][128 * BSTR2];   // 2 x 10240 B (n-major)

    const int tid  = threadIdx.x;
    const int warp = tid >> 5;
    const int lane = tid & 31;
    const int wRow = warp >> 1;        // 0..1 (64 rows)
    const int wCol = warp & 1;         // 0..1 (64 cols)
    const int g    = lane >> 2;        // 0..7
    const int t4   = lane & 3;         // 0..3
    const int rowBase = blockIdx.y * 128;
    const int colBase = blockIdx.x * 128;

    float acc[4][8][4];
    #pragma unroll
    for (int mt = 0; mt < 4; mt++)
        #pragma unroll
        for (int nt = 0; nt < 8; nt++)
            #pragma unroll
            for (int r = 0; r < 4; r++) acc[mt][nt][r] = 0.0f;

    const uint32_t aBase[2] = { (uint32_t)__cvta_generic_to_shared(&As[0][0]),
                                (uint32_t)__cvta_generic_to_shared(&As[1][0]) };
    const uint32_t bBase[2] = { (uint32_t)__cvta_generic_to_shared(&Bs[0][0]),
                                (uint32_t)__cvta_generic_to_shared(&Bs[1][0]) };

    // per-thread ldmatrix row/col components
    const int tq   = lane >> 3;            // 0..3 (matrix id for x4)
    const int trow = lane & 7;             // row within matrix
    const int aRowT = wRow * 64 + (tq & 1) * 8 + trow;   // + mt*16
    const int aColT = (tq >> 1) * 4;                     // + kk*8
    const int bRowT = wCol * 64 + trow;                  // + nt*8
    const int bColT = (tq & 1) * 4;                      // + kk*8 (x2: lanes 0-15)

    const int NT = Kd >> 4;

    auto fill_async = [&](int buf, int kt) {
        const int k0 = kt * 16;
        #pragma unroll
        for (int i = 0; i < 4; i++) {
            const int vec = tid + i * GT;      // 0..511
            const int ar  = vec >> 2;          // 0..127
            const int ac4 = vec & 3;
            cp16(aBase[buf] + (uint32_t)(ar * ASTR + ac4 * 4) * 4,
                 &A[(size_t)(rowBase + ar) * lda + k0 + ac4 * 4]);
            const int bn  = vec >> 2;          // 0..127 (n row)
            const int bk4 = vec & 3;
            cp16(bBase[buf] + (uint32_t)(bn * BSTR2 + bk4 * 4) * 4,
                 &Bt[(size_t)(colBase + bn) * Kd + k0 + bk4 * 4]);
        }
        cp_commit();
    };

    fill_async(0, 0);
    cp_wait0();
    __syncthreads();

    for (int kt = 0; kt < NT; kt++) {
        const int buf = kt & 1;
        if (kt + 1 < NT) fill_async(buf ^ 1, kt + 1);

        #pragma unroll
        for (int kk = 0; kk < 2; kk++) {
            uint32_t af[4][4];
            uint32_t bf[8][2];
            #pragma unroll
            for (int mt = 0; mt < 4; mt++)
                ldsm4(af[mt], aBase[buf] +
                      (uint32_t)((aRowT + mt * 16) * ASTR + kk * 8 + aColT) * 4);
            #pragma unroll
            for (int nt = 0; nt < 8; nt++)
                ldsm2(bf[nt], bBase[buf] +
                      (uint32_t)((bRowT + nt * 8) * BSTR2 + kk * 8 + bColT) * 4);
            #pragma unroll
            for (int mt = 0; mt < 4; mt++)
                #pragma unroll
                for (int nt = 0; nt < 8; nt++)
                    mma_tf32(acc[mt][nt], af[mt], bf[nt]);
        }

        if (kt + 1 < NT) {
            cp_wait0();
            __syncthreads();
        }
    }

    // epilogue
    #pragma unroll
    for (int mt = 0; mt < 4; mt++) {
        #pragma unroll
        for (int half = 0; half < 2; half++) {
            const int gr = rowBase + wRow * 64 + mt * 16 + g + half * 8;
            if (gr >= MoutRows) continue;
            const bool pad = (gr >= Mreal);
            #pragma unroll
            for (int nt = 0; nt < 8; nt++) {
                const int gc = colBase + wCol * 64 + nt * 8 + 2 * t4;
                float2 o;
                o.x = pad ? 0.f : acc[mt][nt][half * 2 + 0] + bias[gc + 0];
                o.y = pad ? 0.f : acc[mt][nt][half * 2 + 1] + bias[gc + 1];
                *(float2*)&C[(size_t)gr * ldc + gc] = o;
            }
        }
    }
}

// ---------------------------------------------------------------------------
// Attention: unchanged; in-place output RNA-rounded into the Q region.
// ---------------------------------------------------------------------------
__global__ __launch_bounds__(32 * AW) void attn_kernel(
    const int* __restrict__ bidx, const int* __restrict__ didx)
{
    const int warp = threadIdx.x >> 5;
    const int lane = threadIdx.x & 31;
    const int flat = blockIdx.x * AW + warp;
    const int p = flat >> 4;
    const int h = flat & 15;
    const int group = p >> 2;
    const int dsub  = p & 3;
    const int stride = g_idx64 ? 2 : 1;

    __shared__ float ks[AW][KTOK][HDP];
    __shared__ float vs[AW][KTOK][HDP];
    __shared__ int   sb_[AW][KTOK];
    __shared__ int   sd_[AW][KTOK];

    const int myrow = group * 128 + lane * 4 + dsub;

    if (myrow < N_TOK) {
        sb_[warp][lane] = bidx[(size_t)myrow * stride];
        sd_[warp][lane] = didx[(size_t)myrow * stride];
    } else {
        sb_[warp][lane] = 0;
        sd_[warp][lane] = 0x40000000;
    }

    float* base = &g_qkv[(size_t)myrow * QKV_N];
    {
        const float4* kp = (const float4*)(base + CDIM + h * HD);
        const float4* vp = (const float4*)(base + 2 * CDIM + h * HD);
        #pragma unroll
        for (int i = 0; i < 16; i++) {
            ((float4*)ks[warp][lane])[i] = kp[i];
            ((float4*)vs[warp][lane])[i] = vp[i];
        }
    }
    float4 q[16];
    {
        const float4* qp = (const float4*)(base + h * HD);
        #pragma unroll
        for (int i = 0; i < 16; i++) q[i] = qp[i];
    }
    __syncwarp();

    const int myb = sb_[warp][lane];
    const int myd = sd_[warp][lane];

    float sc[KTOK];
    float mx = -3.4e38f;
    #pragma unroll
    for (int j = 0; j < KTOK; j++) {
        float4 a4 = make_float4(0.f, 0.f, 0.f, 0.f);
        const float4* kj = (const float4*)ks[warp][j];
        #pragma unroll
        for (int i = 0; i < 16; i++) {
            const float4 kv = kj[i];
            a4.x = fmaf(q[i].x, kv.x, a4.x);
            a4.y = fmaf(q[i].y, kv.y, a4.y);
            a4.z = fmaf(q[i].z, kv.z, a4.z);
            a4.w = fmaf(q[i].w, kv.w, a4.w);
        }
        float s = ((a4.x + a4.y) + (a4.z + a4.w)) * 0.125f;
        if (myb != sb_[warp][j]) s -= 1000.0f;
        if (myd <  sd_[warp][j]) s -= 1000.0f;
        sc[j] = s;
        mx = fmaxf(mx, s);
    }

    float sum = 0.0f;
    #pragma unroll
    for (int j = 0; j < KTOK; j++) {
        sc[j] = __expf(sc[j] - mx);
        sum += sc[j];
    }
    const float inv = 1.0f / sum;

    float4 o[16];
    #pragma unroll
    for (int i = 0; i < 16; i++) o[i] = make_float4(0.f, 0.f, 0.f, 0.f);
    #pragma unroll
    for (int j = 0; j < KTOK; j++) {
        const float a = sc[j] * inv;
        const float4* vj = (const float4*)vs[warp][j];
        #pragma unroll
        for (int i = 0; i < 16; i++) {
            const float4 vv = vj[i];
            o[i].x = fmaf(a, vv.x, o[i].x);
            o[i].y = fmaf(a, vv.y, o[i].y);
            o[i].z = fmaf(a, vv.z, o[i].z);
            o[i].w = fmaf(a, vv.w, o[i].w);
        }
    }

    float4* op = (float4*)(base + h * HD);
    #pragma unroll
    for (int i = 0; i < 16; i++) {
        op[i] = make_float4(f2tf_f(o[i].x), f2tf_f(o[i].y),
                            f2tf_f(o[i].z), f2tf_f(o[i].w));
    }
}

// ---------------------------------------------------------------------------
extern "C" void kernel_launch(void* const* d_in, const int* in_sizes, int n_in,
                              void* d_out, int out_size)
{
    const float* data   = (const float*)d_in[0];
    const float* w_qkv  = (const float*)d_in[1];
    const float* b_qkv  = (const float*)d_in[2];
    const float* w_proj = (const float*)d_in[3];
    const float* b_proj = (const float*)d_in[4];
    const int*   bidx   = (const int*)d_in[5];
    const int*   didx   = (const int*)d_in[6];
    (void)in_sizes; (void)n_in; (void)out_size;

    float* qkv_ptr = nullptr;
    float* aux_ptr = nullptr;
    cudaGetSymbolAddress((void**)&qkv_ptr, g_qkv);
    cudaGetSymbolAddress((void**)&aux_ptr, g_aux);
    float* dataR   = aux_ptr + AUX_DATA;
    float* wqkvT   = aux_ptr + AUX_WQKV;
    float* wprojT  = aux_ptr + AUX_WPROJ;

    detect_idx_kernel<<<1, 256>>>(bidx);

    // Pre-round data (pad rows zeroed); round+TRANSPOSE weights to [n][k].
    {
        const int n4r = (N_TOK * CDIM) / 4, n4t = (NPAD * CDIM) / 4;
        round_kernel<<<(n4t + 255) / 256, 256>>>((const float4*)data,
                                                 (float4*)dataR, n4r, n4t);
        round_transpose<<<dim3(QKV_N / 32, CDIM / 32), dim3(32, 8)>>>(
            w_qkv, wqkvT, CDIM, QKV_N);
        round_transpose<<<dim3(CDIM / 32, CDIM / 32), dim3(32, 8)>>>(
            w_proj, wprojT, CDIM, CDIM);
    }

    // qkv = data @ w_qkv + b_qkv, pad rows -> exact 0
    dim3 g1(QKV_N / 128, NPAD / 128);
    tf32_gemm<<<g1, GT>>>(dataR, wqkvT, b_qkv, qkv_ptr,
                          QKV_N, CDIM, CDIM, QKV_N, N_TOK, NPAD);

    // blocked attention; rounded output in-place into Q region
    attn_kernel<<<(2048 * HEADS) / AW, 32 * AW>>>(bidx, didx);

    // out = attn_out @ w_proj + b_proj (A = Q region of g_qkv, lda=3072)
    dim3 g2(CDIM / 128, NPAD / 128);
    tf32_gemm<<<g2, GT>>>(qkv_ptr, wprojT, b_proj, (float*)d_out,
                          CDIM, CDIM, QKV_N, CDIM, NPAD, N_TOK);
}

// round 16
// speedup vs baseline: 1.7389x; 1.6642x over previous
#include <cuda_runtime.h>
#include <cuda_fp16.h>
#include <cstdint>
#include <cstring>

#define N_TOK  65529
#define NPAD   65536
#define CDIM   1024
#define QKV_N  3072
#define HEADS  16
#define HD     64
#define HDP    68
#define KTOK   32
#define AW     2

// gemm config: 128x128 CTA tile, 4 warps, 64x64 per warp, BK=32 (2x k16),
// fp16 m16n8k16 MMA, 2-stage cp.async, ldmatrix fragments.
#define GT     128
#define ASTRH  40    // smem row stride in halfs (80B) — conflict-free ldmatrix

// fp16 scratch layout (halfs)
#define H_DATA  0
#define H_ATT   ((size_t)NPAD * CDIM)
#define H_WQKV  (2 * (size_t)NPAD * CDIM)
#define H_WPROJ (H_WQKV + (size_t)CDIM * QKV_N)
#define H_TOTAL (H_WPROJ + (size_t)CDIM * CDIM)

__device__ float  g_qkv[(size_t)NPAD * QKV_N];   // 805 MB (fp32 qkv)
__device__ __half g_h[H_TOTAL];                  // 277 MB (fp16 data/att/weights)
__device__ int    g_idx64;

// ---------------------------------------------------------------------------
__device__ __forceinline__ uint32_t h2u(__half2 v) {
    uint32_t r;
    memcpy(&r, &v, 4);
    return r;
}

// ---------------------------------------------------------------------------
__global__ void detect_idx_kernel(const int* __restrict__ b) {
    __shared__ int s;
    if (threadIdx.x == 0) s = 0;
    __syncthreads();
    int local = 0;
    for (int i = threadIdx.x; i < (N_TOK / 2) - 1; i += blockDim.x) {
        int lo = b[2 * i], hi = b[2 * i + 1];
        if (lo > 0 && hi == 0) local = 1;
    }
    if (local) atomicOr(&s, 1);
    __syncthreads();
    if (threadIdx.x == 0) g_idx64 = s;
}

// ---------------------------------------------------------------------------
// fp32 -> fp16 (RN): src[0..n8r) converted, [n8r..n8t) zeroed. 8 floats/thread.
__global__ void tohalf_kernel(const float4* __restrict__ src,
                              uint4* __restrict__ dst, int n8r, int n8t)
{
    const int i = blockIdx.x * blockDim.x + threadIdx.x;
    if (i >= n8t) return;
    uint4 o = make_uint4(0u, 0u, 0u, 0u);
    if (i < n8r) {
        const float4 a = src[2 * i];
        const float4 b = src[2 * i + 1];
        o.x = h2u(__floats2half2_rn(a.x, a.y));
        o.y = h2u(__floats2half2_rn(a.z, a.w));
        o.z = h2u(__floats2half2_rn(b.x, b.y));
        o.w = h2u(__floats2half2_rn(b.z, b.w));
    }
    dst[i] = o;
}

// fp32 src[R][C] -> fp16 dst[C][R] (transpose). R,C multiples of 32.
__global__ void tohalf_transpose(const float* __restrict__ src,
                                 __half* __restrict__ dst, int R, int C)
{
    __shared__ float t[32][33];
    const int c0 = blockIdx.x * 32, r0 = blockIdx.y * 32;
    #pragma unroll
    for (int i = threadIdx.y; i < 32; i += 8)
        t[i][threadIdx.x] = src[(size_t)(r0 + i) * C + c0 + threadIdx.x];
    __syncthreads();
    #pragma unroll
    for (int i = threadIdx.y; i < 32; i += 8)
        dst[(size_t)(c0 + i) * R + r0 + threadIdx.x] =
            __float2half_rn(t[threadIdx.x][i]);
}

// ---------------------------------------------------------------------------
__device__ __forceinline__ void mma_f16(float* c, const uint32_t* a, const uint32_t* b) {
    asm volatile(
        "mma.sync.aligned.m16n8k16.row.col.f32.f16.f16.f32 "
        "{%0,%1,%2,%3}, {%4,%5,%6,%7}, {%8,%9}, {%0,%1,%2,%3};"
        : "+f"(c[0]), "+f"(c[1]), "+f"(c[2]), "+f"(c[3])
        : "r"(a[0]), "r"(a[1]), "r"(a[2]), "r"(a[3]),
          "r"(b[0]), "r"(b[1]));
}
__device__ __forceinline__ void ldsm4(uint32_t* r, uint32_t addr) {
    asm volatile("ldmatrix.sync.aligned.m8n8.x4.shared.b16 {%0,%1,%2,%3}, [%4];"
                 : "=r"(r[0]), "=r"(r[1]), "=r"(r[2]), "=r"(r[3]) : "r"(addr));
}
__device__ __forceinline__ void ldsm2(uint32_t* r, uint32_t addr) {
    asm volatile("ldmatrix.sync.aligned.m8n8.x2.shared.b16 {%0,%1}, [%2];"
                 : "=r"(r[0]), "=r"(r[1]) : "r"(addr));
}
__device__ __forceinline__ void cp16(uint32_t saddr, const void* g) {
    asm volatile("cp.async.cg.shared.global [%0], [%1], 16;"
                 :: "r"(saddr), "l"(g) : "memory");
}
__device__ __forceinline__ void cp_commit() {
    asm volatile("cp.async.commit_group;" ::: "memory");
}
__device__ __forceinline__ void cp_wait0() {
    asm volatile("cp.async.wait_group 0;" ::: "memory");
}

// ---------------------------------------------------------------------------
// FP16 tensor-core GEMM: 128x128 CTA tile, BK=32, 128 threads, 4 warps,
// 64x64 per warp via m16n8k16. A: [rows][Kd] fp16 row-major (stride lda,
// pad rows pre-zeroed). Bt: [Nc][Kd] fp16 (transposed weight, n-major).
// C (fp32) = A*B + bias;  rows >= Mreal -> exact 0;  rows >= MoutRows unwritten.
// ---------------------------------------------------------------------------
__global__ __launch_bounds__(GT, 2) void f16_gemm(
    const __half* __restrict__ A, const __half* __restrict__ Bt,
    const float* __restrict__ bias, float* __restrict__ C,
    int Nc, int Kd, int lda, int ldc, int Mreal, int MoutRows)
{
    __shared__ __half As[2][128 * ASTRH];   // 2 x 10240 B
    __shared__ __half Bs[2][128 * ASTRH];   // 2 x 10240 B (n-major)

    const int tid  = threadIdx.x;
    const int warp = tid >> 5;
    const int lane = tid & 31;
    const int wRow = warp >> 1;        // 0..1 (64 rows)
    const int wCol = warp & 1;         // 0..1 (64 cols)
    const int g    = lane >> 2;        // 0..7
    const int t4   = lane & 3;         // 0..3
    const int rowBase = blockIdx.y * 128;
    const int colBase = blockIdx.x * 128;

    float acc[4][8][4];
    #pragma unroll
    for (int mt = 0; mt < 4; mt++)
        #pragma unroll
        for (int nt = 0; nt < 8; nt++)
            #pragma unroll
            for (int r = 0; r < 4; r++) acc[mt][nt][r] = 0.0f;

    const uint32_t aBase[2] = { (uint32_t)__cvta_generic_to_shared(&As[0][0]),
                                (uint32_t)__cvta_generic_to_shared(&As[1][0]) };
    const uint32_t bBase[2] = { (uint32_t)__cvta_generic_to_shared(&Bs[0][0]),
                                (uint32_t)__cvta_generic_to_shared(&Bs[1][0]) };

    // ldmatrix per-lane address components (half units)
    const int tq   = lane >> 3;                          // 0..3
    const int trow = lane & 7;
    const int aRowT = wRow * 64 + (tq & 1) * 8 + trow;   // + mt*16
    const int aColH = (tq >> 1) * 8;                     // + kk*16
    const int bRowT = wCol * 64 + trow;                  // + nt*8
    const int bColH = (tq & 1) * 8;                      // + kk*16 (x2 uses lanes 0-15)

    const int NT = Kd >> 5;   // 32-k tiles

    auto fill_async = [&](int buf, int kt) {
        const int k0 = kt * 32;
        #pragma unroll
        for (int i = 0; i < 4; i++) {
            const int vec = tid + i * GT;      // 0..511
            const int ar = vec >> 2;           // 0..127
            const int ac = vec & 3;            // chunk of 8 halfs
            cp16(aBase[buf] + (uint32_t)(ar * ASTRH + ac * 8) * 2,
                 &A[(size_t)(rowBase + ar) * lda + k0 + ac * 8]);
            const int bn = vec >> 2;
            const int bk = vec & 3;
            cp16(bBase[buf] + (uint32_t)(bn * ASTRH + bk * 8) * 2,
                 &Bt[(size_t)(colBase + bn) * Kd + k0 + bk * 8]);
        }
        cp_commit();
    };

    fill_async(0, 0);
    cp_wait0();
    __syncthreads();

    for (int kt = 0; kt < NT; kt++) {
        const int buf = kt & 1;
        if (kt + 1 < NT) fill_async(buf ^ 1, kt + 1);

        #pragma unroll
        for (int kk = 0; kk < 2; kk++) {
            uint32_t af[4][4];
            uint32_t bf[8][2];
            #pragma unroll
            for (int mt = 0; mt < 4; mt++)
                ldsm4(af[mt], aBase[buf] +
                      (uint32_t)((aRowT + mt * 16) * ASTRH + kk * 16 + aColH) * 2);
            #pragma unroll
            for (int nt = 0; nt < 8; nt++)
                ldsm2(bf[nt], bBase[buf] +
                      (uint32_t)((bRowT + nt * 8) * ASTRH + kk * 16 + bColH) * 2);
            #pragma unroll
            for (int mt = 0; mt < 4; mt++)
                #pragma unroll
                for (int nt = 0; nt < 8; nt++)
                    mma_f16(acc[mt][nt], af[mt], bf[nt]);
        }

        if (kt + 1 < NT) {
            cp_wait0();
            __syncthreads();
        }
    }

    // epilogue (fp32)
    #pragma unroll
    for (int mt = 0; mt < 4; mt++) {
        #pragma unroll
        for (int half_ = 0; half_ < 2; half_++) {
            const int gr = rowBase + wRow * 64 + mt * 16 + g + half_ * 8;
            if (gr >= MoutRows) continue;
            const bool pad = (gr >= Mreal);
            #pragma unroll
            for (int nt = 0; nt < 8; nt++) {
                const int gc = colBase + wCol * 64 + nt * 8 + 2 * t4;
                float2 o;
                o.x = pad ? 0.f : acc[mt][nt][half_ * 2 + 0] + bias[gc + 0];
                o.y = pad ? 0.f : acc[mt][nt][half_ * 2 + 1] + bias[gc + 1];
                *(float2*)&C[(size_t)gr * ldc + gc] = o;
            }
        }
    }
}

// ---------------------------------------------------------------------------
// Attention: fp32 math on fp32 qkv (unchanged); output stored fp16 to g_h[H_ATT].
// ---------------------------------------------------------------------------
__global__ __launch_bounds__(32 * AW) void attn_kernel(
    const int* __restrict__ bidx, const int* __restrict__ didx)
{
    const int warp = threadIdx.x >> 5;
    const int lane = threadIdx.x & 31;
    const int flat = blockIdx.x * AW + warp;
    const int p = flat >> 4;
    const int h = flat & 15;
    const int group = p >> 2;
    const int dsub  = p & 3;
    const int stride = g_idx64 ? 2 : 1;

    __shared__ float ks[AW][KTOK][HDP];
    __shared__ float vs[AW][KTOK][HDP];
    __shared__ int   sb_[AW][KTOK];
    __shared__ int   sd_[AW][KTOK];

    const int myrow = group * 128 + lane * 4 + dsub;

    if (myrow < N_TOK) {
        sb_[warp][lane] = bidx[(size_t)myrow * stride];
        sd_[warp][lane] = didx[(size_t)myrow * stride];
    } else {
        sb_[warp][lane] = 0;
        sd_[warp][lane] = 0x40000000;
    }

    const float* base = &g_qkv[(size_t)myrow * QKV_N];
    {
        const float4* kp = (const float4*)(base + CDIM + h * HD);
        const float4* vp = (const float4*)(base + 2 * CDIM + h * HD);
        #pragma unroll
        for (int i = 0; i < 16; i++) {
            ((float4*)ks[warp][lane])[i] = kp[i];
            ((float4*)vs[warp][lane])[i] = vp[i];
        }
    }
    float4 q[16];
    {
        const float4* qp = (const float4*)(base + h * HD);
        #pragma unroll
        for (int i = 0; i < 16; i++) q[i] = qp[i];
    }
    __syncwarp();

    const int myb = sb_[warp][lane];
    const int myd = sd_[warp][lane];

    float sc[KTOK];
    float mx = -3.4e38f;
    #pragma unroll
    for (int j = 0; j < KTOK; j++) {
        float4 a4 = make_float4(0.f, 0.f, 0.f, 0.f);
        const float4* kj = (const float4*)ks[warp][j];
        #pragma unroll
        for (int i = 0; i < 16; i++) {
            const float4 kv = kj[i];
            a4.x = fmaf(q[i].x, kv.x, a4.x);
            a4.y = fmaf(q[i].y, kv.y, a4.y);
            a4.z = fmaf(q[i].z, kv.z, a4.z);
            a4.w = fmaf(q[i].w, kv.w, a4.w);
        }
        float s = ((a4.x + a4.y) + (a4.z + a4.w)) * 0.125f;
        if (myb != sb_[warp][j]) s -= 1000.0f;
        if (myd <  sd_[warp][j]) s -= 1000.0f;
        sc[j] = s;
        mx = fmaxf(mx, s);
    }

    float sum = 0.0f;
    #pragma unroll
    for (int j = 0; j < KTOK; j++) {
        sc[j] = __expf(sc[j] - mx);
        sum += sc[j];
    }
    const float inv = 1.0f / sum;

    float4 o[16];
    #pragma unroll
    for (int i = 0; i < 16; i++) o[i] = make_float4(0.f, 0.f, 0.f, 0.f);
    #pragma unroll
    for (int j = 0; j < KTOK; j++) {
        const float a = sc[j] * inv;
        const float4* vj = (const float4*)vs[warp][j];
        #pragma unroll
        for (int i = 0; i < 16; i++) {
            const float4 vv = vj[i];
            o[i].x = fmaf(a, vv.x, o[i].x);
            o[i].y = fmaf(a, vv.y, o[i].y);
            o[i].z = fmaf(a, vv.z, o[i].z);
            o[i].w = fmaf(a, vv.w, o[i].w);
        }
    }

    // fp16 output to dedicated buffer: row myrow, halfs [h*64, h*64+64)
    uint4* op = (uint4*)&g_h[H_ATT + (size_t)myrow * CDIM + h * HD];
    #pragma unroll
    for (int i = 0; i < 16; i += 2) {
        uint4 w;
        w.x = h2u(__floats2half2_rn(o[i].x,     o[i].y));
        w.y = h2u(__floats2half2_rn(o[i].z,     o[i].w));
        w.z = h2u(__floats2half2_rn(o[i + 1].x, o[i + 1].y));
        w.w = h2u(__floats2half2_rn(o[i + 1].z, o[i + 1].w));
        op[i >> 1] = w;
    }
}

// ---------------------------------------------------------------------------
extern "C" void kernel_launch(void* const* d_in, const int* in_sizes, int n_in,
                              void* d_out, int out_size)
{
    const float* data   = (const float*)d_in[0];
    const float* w_qkv  = (const float*)d_in[1];
    const float* b_qkv  = (const float*)d_in[2];
    const float* w_proj = (const float*)d_in[3];
    const float* b_proj = (const float*)d_in[4];
    const int*   bidx   = (const int*)d_in[5];
    const int*   didx   = (const int*)d_in[6];
    (void)in_sizes; (void)n_in; (void)out_size;

    float*  qkv_ptr = nullptr;
    __half* h_ptr   = nullptr;
    cudaGetSymbolAddress((void**)&qkv_ptr, g_qkv);
    cudaGetSymbolAddress((void**)&h_ptr, g_h);
    __half* dataH  = h_ptr + H_DATA;
    __half* attH   = h_ptr + H_ATT;
    __half* wqkvT  = h_ptr + H_WQKV;
    __half* wprojT = h_ptr + H_WPROJ;

    detect_idx_kernel<<<1, 256>>>(bidx);

    // Convert data -> fp16 (pad rows zeroed); weights -> transposed fp16.
    {
        const int n8r = (N_TOK * CDIM) / 8, n8t = (NPAD * CDIM) / 8;
        tohalf_kernel<<<(n8t + 255) / 256, 256>>>((const float4*)data,
                                                  (uint4*)dataH, n8r, n8t);
        tohalf_transpose<<<dim3(QKV_N / 32, CDIM / 32), dim3(32, 8)>>>(
            w_qkv, wqkvT, CDIM, QKV_N);
        tohalf_transpose<<<dim3(CDIM / 32, CDIM / 32), dim3(32, 8)>>>(
            w_proj, wprojT, CDIM, CDIM);
    }

    // qkv (fp32) = dataH @ wqkvT + b_qkv, pad rows -> exact 0
    dim3 g1(QKV_N / 128, NPAD / 128);
    f16_gemm<<<g1, GT>>>(dataH, wqkvT, b_qkv, qkv_ptr,
                         QKV_N, CDIM, CDIM, QKV_N, N_TOK, NPAD);

    // blocked attention (fp32 math); fp16 output to attH
    attn_kernel<<<(2048 * HEADS) / AW, 32 * AW>>>(bidx, didx);

    // out (fp32) = attH @ wprojT + b_proj
    dim3 g2(CDIM / 128, NPAD / 128);
    f16_gemm<<<g2, GT>>>(attH, wprojT, b_proj, (float*)d_out,
                         CDIM, CDIM, CDIM, CDIM, NPAD, N_TOK);
}

// round 17
// speedup vs baseline: 1.8398x; 1.0580x over previous
#include <cuda_runtime.h>
#include <cuda_fp16.h>
#include <cstdint>
#include <cstring>

#define N_TOK  65529
#define NPAD   65536
#define CDIM   1024
#define QKV_N  3072
#define HEADS  16
#define HD     64
#define HDP    68
#define KTOK   32
#define AW     2

// gemm config: 128x128 CTA tile, 4 warps, 64x64 per warp, BK=32 (2x k16),
// fp16 m16n8k16 MMA, 2-stage cp.async, ldmatrix fragments.
#define GT     128
#define ASTRH  40    // smem row stride in halfs (80B) — conflict-free ldmatrix

// fp16 scratch layout (halfs). qkv itself is now fp16 (no fp32 buffer at all).
#define H_DATA  0
#define H_ATT   ((size_t)NPAD * CDIM)
#define H_QKV   (2 * (size_t)NPAD * CDIM)
#define H_WQKV  (H_QKV + (size_t)NPAD * QKV_N)
#define H_WPROJ (H_WQKV + (size_t)CDIM * QKV_N)
#define H_TOTAL (H_WPROJ + (size_t)CDIM * CDIM)

__device__ __half g_h[H_TOTAL];                  // ~680 MB
__device__ int    g_idx64;

// ---------------------------------------------------------------------------
__device__ __forceinline__ uint32_t h2u(__half2 v) {
    uint32_t r;
    memcpy(&r, &v, 4);
    return r;
}
__device__ __forceinline__ float2 u2f2(uint32_t u) {
    __half2 h;
    memcpy(&h, &u, 4);
    return __half22float2(h);
}

// ---------------------------------------------------------------------------
__global__ void detect_idx_kernel(const int* __restrict__ b) {
    __shared__ int s;
    if (threadIdx.x == 0) s = 0;
    __syncthreads();
    int local = 0;
    for (int i = threadIdx.x; i < (N_TOK / 2) - 1; i += blockDim.x) {
        int lo = b[2 * i], hi = b[2 * i + 1];
        if (lo > 0 && hi == 0) local = 1;
    }
    if (local) atomicOr(&s, 1);
    __syncthreads();
    if (threadIdx.x == 0) g_idx64 = s;
}

// ---------------------------------------------------------------------------
// fp32 -> fp16 (RN): src[0..n8r) converted, [n8r..n8t) zeroed. 8 floats/thread.
__global__ void tohalf_kernel(const float4* __restrict__ src,
                              uint4* __restrict__ dst, int n8r, int n8t)
{
    const int i = blockIdx.x * blockDim.x + threadIdx.x;
    if (i >= n8t) return;
    uint4 o = make_uint4(0u, 0u, 0u, 0u);
    if (i < n8r) {
        const float4 a = src[2 * i];
        const float4 b = src[2 * i + 1];
        o.x = h2u(__floats2half2_rn(a.x, a.y));
        o.y = h2u(__floats2half2_rn(a.z, a.w));
        o.z = h2u(__floats2half2_rn(b.x, b.y));
        o.w = h2u(__floats2half2_rn(b.z, b.w));
    }
    dst[i] = o;
}

// fp32 src[R][C] -> fp16 dst[C][R] (transpose). R,C multiples of 32.
__global__ void tohalf_transpose(const float* __restrict__ src,
                                 __half* __restrict__ dst, int R, int C)
{
    __shared__ float t[32][33];
    const int c0 = blockIdx.x * 32, r0 = blockIdx.y * 32;
    #pragma unroll
    for (int i = threadIdx.y; i < 32; i += 8)
        t[i][threadIdx.x] = src[(size_t)(r0 + i) * C + c0 + threadIdx.x];
    __syncthreads();
    #pragma unroll
    for (int i = threadIdx.y; i < 32; i += 8)
        dst[(size_t)(c0 + i) * R + r0 + threadIdx.x] =
            __float2half_rn(t[threadIdx.x][i]);
}

// ---------------------------------------------------------------------------
__device__ __forceinline__ void mma_f16(float* c, const uint32_t* a, const uint32_t* b) {
    asm volatile(
        "mma.sync.aligned.m16n8k16.row.col.f32.f16.f16.f32 "
        "{%0,%1,%2,%3}, {%4,%5,%6,%7}, {%8,%9}, {%0,%1,%2,%3};"
        : "+f"(c[0]), "+f"(c[1]), "+f"(c[2]), "+f"(c[3])
        : "r"(a[0]), "r"(a[1]), "r"(a[2]), "r"(a[3]),
          "r"(b[0]), "r"(b[1]));
}
__device__ __forceinline__ void ldsm4(uint32_t* r, uint32_t addr) {
    asm volatile("ldmatrix.sync.aligned.m8n8.x4.shared.b16 {%0,%1,%2,%3}, [%4];"
                 : "=r"(r[0]), "=r"(r[1]), "=r"(r[2]), "=r"(r[3]) : "r"(addr));
}
__device__ __forceinline__ void ldsm2(uint32_t* r, uint32_t addr) {
    asm volatile("ldmatrix.sync.aligned.m8n8.x2.shared.b16 {%0,%1}, [%2];"
                 : "=r"(r[0]), "=r"(r[1]) : "r"(addr));
}
__device__ __forceinline__ void cp16(uint32_t saddr, const void* g) {
    asm volatile("cp.async.cg.shared.global [%0], [%1], 16;"
                 :: "r"(saddr), "l"(g) : "memory");
}
__device__ __forceinline__ void cp_commit() {
    asm volatile("cp.async.commit_group;" ::: "memory");
}
__device__ __forceinline__ void cp_wait0() {
    asm volatile("cp.async.wait_group 0;" ::: "memory");
}

// output helpers: fp32 or fp16 C
__device__ __forceinline__ void store2(float* p, float x, float y) {
    *(float2*)p = make_float2(x, y);
}
__device__ __forceinline__ void store2(__half* p, float x, float y) {
    *(uint32_t*)p = h2u(__floats2half2_rn(x, y));
}

// ---------------------------------------------------------------------------
// FP16 tensor-core GEMM: 128x128 CTA tile, BK=32, 128 threads, 4 warps,
// 64x64 per warp via m16n8k16. A: [rows][Kd] fp16 row-major (stride lda,
// pad rows pre-zeroed). Bt: [Nc][Kd] fp16 (transposed weight, n-major).
// C (OutT) = A*B + bias;  rows >= Mreal -> exact 0;  rows >= MoutRows unwritten.
// ---------------------------------------------------------------------------
template <typename OutT>
__global__ __launch_bounds__(GT, 2) void f16_gemm(
    const __half* __restrict__ A, const __half* __restrict__ Bt,
    const float* __restrict__ bias, OutT* __restrict__ C,
    int Nc, int Kd, int lda, int ldc, int Mreal, int MoutRows)
{
    __shared__ __half As[2][128 * ASTRH];   // 2 x 10240 B
    __shared__ __half Bs[2][128 * ASTRH];   // 2 x 10240 B (n-major)

    const int tid  = threadIdx.x;
    const int warp = tid >> 5;
    const int lane = tid & 31;
    const int wRow = warp >> 1;        // 0..1 (64 rows)
    const int wCol = warp & 1;         // 0..1 (64 cols)
    const int g    = lane >> 2;        // 0..7
    const int t4   = lane & 3;         // 0..3
    const int rowBase = blockIdx.y * 128;
    const int colBase = blockIdx.x * 128;

    float acc[4][8][4];
    #pragma unroll
    for (int mt = 0; mt < 4; mt++)
        #pragma unroll
        for (int nt = 0; nt < 8; nt++)
            #pragma unroll
            for (int r = 0; r < 4; r++) acc[mt][nt][r] = 0.0f;

    const uint32_t aBase[2] = { (uint32_t)__cvta_generic_to_shared(&As[0][0]),
                                (uint32_t)__cvta_generic_to_shared(&As[1][0]) };
    const uint32_t bBase[2] = { (uint32_t)__cvta_generic_to_shared(&Bs[0][0]),
                                (uint32_t)__cvta_generic_to_shared(&Bs[1][0]) };

    // ldmatrix per-lane address components (half units)
    const int tq   = lane >> 3;                          // 0..3
    const int trow = lane & 7;
    const int aRowT = wRow * 64 + (tq & 1) * 8 + trow;   // + mt*16
    const int aColH = (tq >> 1) * 8;                     // + kk*16
    const int bRowT = wCol * 64 + trow;                  // + nt*8
    const int bColH = (tq & 1) * 8;                      // + kk*16 (x2 uses lanes 0-15)

    const int NT = Kd >> 5;   // 32-k tiles

    auto fill_async = [&](int buf, int kt) {
        const int k0 = kt * 32;
        #pragma unroll
        for (int i = 0; i < 4; i++) {
            const int vec = tid + i * GT;      // 0..511
            const int ar = vec >> 2;           // 0..127
            const int ac = vec & 3;            // chunk of 8 halfs
            cp16(aBase[buf] + (uint32_t)(ar * ASTRH + ac * 8) * 2,
                 &A[(size_t)(rowBase + ar) * lda + k0 + ac * 8]);
            const int bn = vec >> 2;
            const int bk = vec & 3;
            cp16(bBase[buf] + (uint32_t)(bn * ASTRH + bk * 8) * 2,
                 &Bt[(size_t)(colBase + bn) * Kd + k0 + bk * 8]);
        }
        cp_commit();
    };

    fill_async(0, 0);
    cp_wait0();
    __syncthreads();

    for (int kt = 0; kt < NT; kt++) {
        const int buf = kt & 1;
        if (kt + 1 < NT) fill_async(buf ^ 1, kt + 1);

        #pragma unroll
        for (int kk = 0; kk < 2; kk++) {
            uint32_t af[4][4];
            uint32_t bf[8][2];
            #pragma unroll
            for (int mt = 0; mt < 4; mt++)
                ldsm4(af[mt], aBase[buf] +
                      (uint32_t)((aRowT + mt * 16) * ASTRH + kk * 16 + aColH) * 2);
            #pragma unroll
            for (int nt = 0; nt < 8; nt++)
                ldsm2(bf[nt], bBase[buf] +
                      (uint32_t)((bRowT + nt * 8) * ASTRH + kk * 16 + bColH) * 2);
            #pragma unroll
            for (int mt = 0; mt < 4; mt++)
                #pragma unroll
                for (int nt = 0; nt < 8; nt++)
                    mma_f16(acc[mt][nt], af[mt], bf[nt]);
        }

        if (kt + 1 < NT) {
            cp_wait0();
            __syncthreads();
        }
    }

    // epilogue (fp32 accumulate + bias, store as OutT)
    #pragma unroll
    for (int mt = 0; mt < 4; mt++) {
        #pragma unroll
        for (int half_ = 0; half_ < 2; half_++) {
            const int gr = rowBase + wRow * 64 + mt * 16 + g + half_ * 8;
            if (gr >= MoutRows) continue;
            const bool pad = (gr >= Mreal);
            #pragma unroll
            for (int nt = 0; nt < 8; nt++) {
                const int gc = colBase + wCol * 64 + nt * 8 + 2 * t4;
                const float ox = pad ? 0.f : acc[mt][nt][half_ * 2 + 0] + bias[gc + 0];
                const float oy = pad ? 0.f : acc[mt][nt][half_ * 2 + 1] + bias[gc + 1];
                store2(&C[(size_t)gr * ldc + gc], ox, oy);
            }
        }
    }
}

// ---------------------------------------------------------------------------
// Attention: fp16 Q/K/V in, fp32 math, fp16 out to g_h[H_ATT].
// ---------------------------------------------------------------------------
__global__ __launch_bounds__(32 * AW) void attn_kernel(
    const int* __restrict__ bidx, const int* __restrict__ didx)
{
    const int warp = threadIdx.x >> 5;
    const int lane = threadIdx.x & 31;
    const int flat = blockIdx.x * AW + warp;
    const int p = flat >> 4;
    const int h = flat & 15;
    const int group = p >> 2;
    const int dsub  = p & 3;
    const int stride = g_idx64 ? 2 : 1;

    __shared__ float ks[AW][KTOK][HDP];
    __shared__ float vs[AW][KTOK][HDP];
    __shared__ int   sb_[AW][KTOK];
    __shared__ int   sd_[AW][KTOK];

    const int myrow = group * 128 + lane * 4 + dsub;

    if (myrow < N_TOK) {
        sb_[warp][lane] = bidx[(size_t)myrow * stride];
        sd_[warp][lane] = didx[(size_t)myrow * stride];
    } else {
        sb_[warp][lane] = 0;
        sd_[warp][lane] = 0x40000000;
    }

    const __half* baseH = &g_h[H_QKV + (size_t)myrow * QKV_N];
    {
        const uint4* kp = (const uint4*)(baseH + CDIM + h * HD);
        const uint4* vp = (const uint4*)(baseH + 2 * CDIM + h * HD);
        #pragma unroll
        for (int i = 0; i < 8; i++) {          // 8 x uint4 = 64 halfs
            const uint4 kw = kp[i];
            const uint4 vw = vp[i];
            float2 f;
            f = u2f2(kw.x); ks[warp][lane][i*8+0] = f.x; ks[warp][lane][i*8+1] = f.y;
            f = u2f2(kw.y); ks[warp][lane][i*8+2] = f.x; ks[warp][lane][i*8+3] = f.y;
            f = u2f2(kw.z); ks[warp][lane][i*8+4] = f.x; ks[warp][lane][i*8+5] = f.y;
            f = u2f2(kw.w); ks[warp][lane][i*8+6] = f.x; ks[warp][lane][i*8+7] = f.y;
            f = u2f2(vw.x); vs[warp][lane][i*8+0] = f.x; vs[warp][lane][i*8+1] = f.y;
            f = u2f2(vw.y); vs[warp][lane][i*8+2] = f.x; vs[warp][lane][i*8+3] = f.y;
            f = u2f2(vw.z); vs[warp][lane][i*8+4] = f.x; vs[warp][lane][i*8+5] = f.y;
            f = u2f2(vw.w); vs[warp][lane][i*8+6] = f.x; vs[warp][lane][i*8+7] = f.y;
        }
    }
    float4 q[16];
    {
        const uint4* qp = (const uint4*)(baseH + h * HD);
        #pragma unroll
        for (int i = 0; i < 8; i++) {
            const uint4 qw = qp[i];
            const float2 f0 = u2f2(qw.x), f1 = u2f2(qw.y);
            const float2 f2 = u2f2(qw.z), f3 = u2f2(qw.w);
            q[i*2]   = make_float4(f0.x, f0.y, f1.x, f1.y);
            q[i*2+1] = make_float4(f2.x, f2.y, f3.x, f3.y);
        }
    }
    __syncwarp();

    const int myb = sb_[warp][lane];
    const int myd = sd_[warp][lane];

    float sc[KTOK];
    float mx = -3.4e38f;
    #pragma unroll
    for (int j = 0; j < KTOK; j++) {
        float4 a4 = make_float4(0.f, 0.f, 0.f, 0.f);
        const float4* kj = (const float4*)ks[warp][j];
        #pragma unroll
        for (int i = 0; i < 16; i++) {
            const float4 kv = kj[i];
            a4.x = fmaf(q[i].x, kv.x, a4.x);
            a4.y = fmaf(q[i].y, kv.y, a4.y);
            a4.z = fmaf(q[i].z, kv.z, a4.z);
            a4.w = fmaf(q[i].w, kv.w, a4.w);
        }
        float s = ((a4.x + a4.y) + (a4.z + a4.w)) * 0.125f;
        if (myb != sb_[warp][j]) s -= 1000.0f;
        if (myd <  sd_[warp][j]) s -= 1000.0f;
        sc[j] = s;
        mx = fmaxf(mx, s);
    }

    float sum = 0.0f;
    #pragma unroll
    for (int j = 0; j < KTOK; j++) {
        sc[j] = __expf(sc[j] - mx);
        sum += sc[j];
    }
    const float inv = 1.0f / sum;

    float4 o[16];
    #pragma unroll
    for (int i = 0; i < 16; i++) o[i] = make_float4(0.f, 0.f, 0.f, 0.f);
    #pragma unroll
    for (int j = 0; j < KTOK; j++) {
        const float a = sc[j] * inv;
        const float4* vj = (const float4*)vs[warp][j];
        #pragma unroll
        for (int i = 0; i < 16; i++) {
            const float4 vv = vj[i];
            o[i].x = fmaf(a, vv.x, o[i].x);
            o[i].y = fmaf(a, vv.y, o[i].y);
            o[i].z = fmaf(a, vv.z, o[i].z);
            o[i].w = fmaf(a, vv.w, o[i].w);
        }
    }

    // fp16 output: row myrow, halfs [h*64, h*64+64)
    uint4* op = (uint4*)&g_h[H_ATT + (size_t)myrow * CDIM + h * HD];
    #pragma unroll
    for (int i = 0; i < 16; i += 2) {
        uint4 w;
        w.x = h2u(__floats2half2_rn(o[i].x,     o[i].y));
        w.y = h2u(__floats2half2_rn(o[i].z,     o[i].w));
        w.z = h2u(__floats2half2_rn(o[i + 1].x, o[i + 1].y));
        w.w = h2u(__floats2half2_rn(o[i + 1].z, o[i + 1].w));
        op[i >> 1] = w;
    }
}

// ---------------------------------------------------------------------------
extern "C" void kernel_launch(void* const* d_in, const int* in_sizes, int n_in,
                              void* d_out, int out_size)
{
    const float* data   = (const float*)d_in[0];
    const float* w_qkv  = (const float*)d_in[1];
    const float* b_qkv  = (const float*)d_in[2];
    const float* w_proj = (const float*)d_in[3];
    const float* b_proj = (const float*)d_in[4];
    const int*   bidx   = (const int*)d_in[5];
    const int*   didx   = (const int*)d_in[6];
    (void)in_sizes; (void)n_in; (void)out_size;

    __half* h_ptr = nullptr;
    cudaGetSymbolAddress((void**)&h_ptr, g_h);
    __half* dataH  = h_ptr + H_DATA;
    __half* attH   = h_ptr + H_ATT;
    __half* qkvH   = h_ptr + H_QKV;
    __half* wqkvT  = h_ptr + H_WQKV;
    __half* wprojT = h_ptr + H_WPROJ;

    detect_idx_kernel<<<1, 256>>>(bidx);

    // Convert data -> fp16 (pad rows zeroed); weights -> transposed fp16.
    {
        const int n8r = (N_TOK * CDIM) / 8, n8t = (NPAD * CDIM) / 8;
        tohalf_kernel<<<(n8t + 255) / 256, 256>>>((const float4*)data,
                                                  (uint4*)dataH, n8r, n8t);
        tohalf_transpose<<<dim3(QKV_N / 32, CDIM / 32), dim3(32, 8)>>>(
            w_qkv, wqkvT, CDIM, QKV_N);
        tohalf_transpose<<<dim3(CDIM / 32, CDIM / 32), dim3(32, 8)>>>(
            w_proj, wprojT, CDIM, CDIM);
    }

    // qkv (fp16) = dataH @ wqkvT + b_qkv, pad rows -> exact 0
    dim3 g1(QKV_N / 128, NPAD / 128);
    f16_gemm<__half><<<g1, GT>>>(dataH, wqkvT, b_qkv, qkvH,
                                 QKV_N, CDIM, CDIM, QKV_N, N_TOK, NPAD);

    // blocked attention (fp32 math on fp16 qkv); fp16 output to attH
    attn_kernel<<<(2048 * HEADS) / AW, 32 * AW>>>(bidx, didx);

    // out (fp32) = attH @ wprojT + b_proj
    dim3 g2(CDIM / 128, NPAD / 128);
    f16_gemm<float><<<g2, GT>>>(attH, wprojT, b_proj, (float*)d_out,
                                CDIM, CDIM, CDIM, CDIM, NPAD, N_TOK);
}